// round 2
// baseline (speedup 1.0000x reference)
#include <cuda_runtime.h>
#include <cstdint>
#include <cstddef>

// ---------------- problem constants ----------------
#define B_    8
#define R_    40
#define L_    128
#define IN_   256
#define WDIM_ 512
#define DREL_ 15
#define F_    200
#define HID_  300
#define KW_   1039      // 4*IN + DREL
#define FPAD_ 256       // filters padded to 256 for clean GEMM tiles
#define KC_   2304      // 9 * 256 (taps x channels)
#define M_    15876     // 126*126 output pixels

// ---------------- device scratch (static: no allocation) ----------------
__device__ float    g_wt[KW_ * IN_];                         // arc_W transposed [1039][256]
__device__ float    g_C[R_ * IN_];                           // rel_embs @ Wr^T  [40][256]
__device__ float    g_px[B_ * L_ * IN_];                     // Wx @ word_h
__device__ float    g_py[B_ * L_ * IN_];                     // Wy @ word_h
__device__ float    g_h[B_ * HID_];                          // filter-factory hidden
__device__ float    g_arc[(size_t)B_ * L_ * L_ * IN_];       // mem_bank, NHWC [b][y][x][c]  (134MB)
__device__ float    g_filtT[(size_t)B_ * KC_ * FPAD_];       // filters [b][k=tap*256+c][f], f>=200 stays 0
__device__ unsigned g_max[B_ * FPAD_];                       // ordered-encoded per-(b,f) max

// ---------------- helpers ----------------
__device__ __forceinline__ float leaky(float v) { return v >= 0.f ? v : 0.01f * v; }

// order-preserving float<->uint encode for atomicMax on floats (incl. negatives)
__device__ __forceinline__ unsigned fenc(float x) {
    unsigned b = __float_as_uint(x);
    return (b & 0x80000000u) ? ~b : (b | 0x80000000u);
}
__device__ __forceinline__ float fdec(unsigned u) {
    return __uint_as_float((u & 0x80000000u) ? (u & 0x7fffffffu) : ~u);
}

// packed fp32x2 math (Blackwell FFMA2): 2x FFMA throughput, PTX-only
__device__ __forceinline__ unsigned long long pk2(float lo, float hi) {
    unsigned long long r;
    asm("mov.b64 %0, {%1, %2};" : "=l"(r) : "f"(lo), "f"(hi));
    return r;
}
__device__ __forceinline__ void upk2(unsigned long long v, float& lo, float& hi) {
    asm("mov.b64 {%0, %1}, %2;" : "=f"(lo), "=f"(hi) : "l"(v));
}
__device__ __forceinline__ unsigned long long fma2(unsigned long long a,
                                                   unsigned long long b,
                                                   unsigned long long c) {
    unsigned long long d;
    asm("fma.rn.f32x2 %0, %1, %2, %3;" : "=l"(d) : "l"(a), "l"(b), "l"(c));
    return d;
}

// ---------------- tiny precompute kernels ----------------

// arc_W [256][1039] -> g_wt [1039][256]
__global__ void k_transpose(const float* __restrict__ arc_W) {
    int k = blockIdx.x, o = threadIdx.x;
    g_wt[k * IN_ + o] = arc_W[o * KW_ + k];
}

// C[r][o] = sum_d rel_embs[r,d] * arc_W[o, 1024+d]
__global__ void k_relC(const float* __restrict__ rel_embs) {
    int o = threadIdx.x;
    for (int r = 0; r < R_; r++) {
        float s = 0.f;
#pragma unroll
        for (int d = 0; d < DREL_; d++)
            s += rel_embs[r * DREL_ + d] * g_wt[(4 * IN_ + d) * IN_ + o];
        g_C[r * IN_ + o] = s;
    }
}

// Px[b,t,o] = sum_k word_h[b,t,k] * arc_W[o,k];  Py uses cols [512,1024)
__global__ void k_P(const float* __restrict__ word_h) {
    int tg = blockIdx.x;      // 0..7 -> 16 tokens each
    int which = blockIdx.y;   // 0:Px 1:Py
    int b = blockIdx.z;
    __shared__ float wh[16][WDIM_];
    int t = threadIdx.x;
    int t0 = tg * 16;
    for (int idx = t; idx < 16 * WDIM_; idx += 256) {
        int tt = idx >> 9, k = idx & 511;
        wh[tt][k] = word_h[((size_t)(b * L_ + t0 + tt)) * WDIM_ + k];
    }
    __syncthreads();
    float acc[16];
#pragma unroll
    for (int i = 0; i < 16; i++) acc[i] = 0.f;
    const float* wtp = g_wt + (size_t)which * WDIM_ * IN_ + t;
    for (int k = 0; k < WDIM_; k++) {
        float w = wtp[(size_t)k * IN_];
#pragma unroll
        for (int tt = 0; tt < 16; tt++) acc[tt] += w * wh[tt][k];
    }
    float* dst = (which ? g_py : g_px) + ((size_t)(b * L_ + t0)) * IN_ + t;
#pragma unroll
    for (int tt = 0; tt < 16; tt++) dst[(size_t)tt * IN_] = acc[tt];
}

// h[b,k] = leaky([e1,e2] @ ff_W[k,:] + ff_b[k]); warp per k
__global__ void k_hidden(const float* __restrict__ e1, const float* __restrict__ e2,
                         const float* __restrict__ ff_W, const float* __restrict__ ff_b) {
    int b = blockIdx.y;
    __shared__ float in_sm[1024];
    int t = threadIdx.x;
    for (int idx = t; idx < 1024; idx += 256)
        in_sm[idx] = idx < 512 ? e1[b * 512 + idx] : e2[b * 512 + idx - 512];
    __syncthreads();
    int w = t >> 5, lane = t & 31;
    int k = blockIdx.x * 8 + w;
    if (k < HID_) {
        float acc = 0.f;
        for (int it = 0; it < 32; it++) {
            int j = it * 32 + lane;
            acc += in_sm[j] * ff_W[(size_t)k * 1024 + j];
        }
#pragma unroll
        for (int off = 16; off; off >>= 1) acc += __shfl_xor_sync(0xffffffffu, acc, off);
        if (!lane) g_h[b * HID_ + k] = leaky(acc + ff_b[k]);
    }
}

// ---------------- arc / mem_bank kernel ----------------
// arc[b,i,j,o] = leaky( m(i,j) * (Px[b,j,o]+Py[b,i,o]) + sum_r relu(E[b,r,i,j])*C[r,o] + arc_b[o] )
__global__ void k_arc(const float* __restrict__ energy, const float* __restrict__ arc_b) {
    int b = blockIdx.z, i = blockIdx.y, j0 = blockIdx.x * 64;
    __shared__ __align__(16) float e_sm[R_][64];
    __shared__ float m_sm[64];
    int t = threadIdx.x;
    const float* ep = energy + (((size_t)b * R_) * L_ + i) * L_ + j0;
    for (int idx = t; idx < R_ * 64; idx += 256) {
        int r = idx >> 6, j = idx & 63;
        float v = ep[(size_t)r * L_ * L_ + j];
        e_sm[r][j] = v < 0.f ? 0.f : v;
    }
    __syncthreads();
    if (t < 64) {
        float s = 0.f;
#pragma unroll
        for (int r = 0; r < R_; r++) s += e_sm[r][t];
        m_sm[t] = s;
    }
    // packed C[r,o] duplicated in both f32x2 lanes
    unsigned long long Creg2[R_];
#pragma unroll
    for (int r = 0; r < R_; r++) {
        float c = g_C[r * IN_ + t];
        Creg2[r] = pk2(c, c);
    }
    float py = g_py[((size_t)(b * L_ + i)) * IN_ + t];
    float bias = arc_b[t];
    __syncthreads();

    float* dst = g_arc + (((size_t)(b * L_ + i)) * L_ + j0) * IN_ + t;
    const float* pxp = g_px + ((size_t)(b * L_) + j0) * IN_ + t;
#pragma unroll 4
    for (int q = 0; q < 16; q++) {
        unsigned long long acc01 = 0ull, acc23 = 0ull;
#pragma unroll
        for (int r = 0; r < R_; r++) {
            // e_sm pairs (j even/odd) read directly as f32x2 lanes (broadcast LDS)
            ulonglong2 ev = *(const ulonglong2*)&e_sm[r][q * 4];
            acc01 = fma2(ev.x, Creg2[r], acc01);
            acc23 = fma2(ev.y, Creg2[r], acc23);
        }
        float av[4];
        upk2(acc01, av[0], av[1]);
        upk2(acc23, av[2], av[3]);
#pragma unroll
        for (int u = 0; u < 4; u++) {
            int j = q * 4 + u;
            float pre = m_sm[j] * (pxp[(size_t)j * IN_] + py) + av[u] + bias;
            dst[(size_t)j * IN_] = leaky(pre);
        }
    }
}

// ---------------- per-sample filters (HBM-bound, 553MB fw1) ----------------
// filtT[b][tap*256+c][f] = leaky(fw1[f,c,tap,:] . h[b] + fb1[f,c,tap]); warp per row
__global__ void k_filt(const float* __restrict__ fw1, const float* __restrict__ fb1) {
    __shared__ float h_sm[B_][HID_];
    int t = threadIdx.x;
    for (int idx = t; idx < B_ * HID_; idx += 256)
        h_sm[idx / HID_][idx % HID_] = g_h[idx];
    __syncthreads();
    int w = t >> 5, lane = t & 31;
    int row = blockIdx.x * 8 + w;          // (f*256+c)*9+tap, < 460800
    float acc[8];
#pragma unroll
    for (int b = 0; b < 8; b++) acc[b] = 0.f;
    const float* wp = fw1 + (size_t)row * HID_;
#pragma unroll
    for (int it = 0; it < 10; it++) {
        int hh = it * 32 + lane;
        float wv = (hh < HID_) ? wp[hh] : 0.f;
        int hc = (hh < HID_) ? hh : 0;
#pragma unroll
        for (int b = 0; b < 8; b++) acc[b] += wv * h_sm[b][hc];
    }
#pragma unroll
    for (int off = 16; off; off >>= 1)
#pragma unroll
        for (int b = 0; b < 8; b++) acc[b] += __shfl_xor_sync(0xffffffffu, acc[b], off);
    if (!lane) {
        int f = row / 2304, rem = row - f * 2304;
        int c = rem / 9, tap = rem - c * 9;
        float bias = fb1[row];
        size_t kidx = (size_t)tap * 256 + c;
#pragma unroll
        for (int b = 0; b < 8; b++)
            g_filtT[((size_t)b * KC_ + kidx) * FPAD_ + f] = leaky(acc[b] + bias);
    }
}

__global__ void k_maxinit() { g_max[blockIdx.x * 1024 + threadIdx.x] = 0u; }

// ---------------- conv as implicit GEMM + fused leaky/maxpool ----------------
// Per b: Out[p,f] = sum_k A[p,k]*Bm[k,f]; A[p,k]=arc[b, y+dy, x+dx, c], k=tap*256+c
// 128x128x8 tiles, 8x8 microtile, f32x2 packed FFMA (pairs along f), double-buffered smem.
__global__ __launch_bounds__(256, 2) void k_conv() {
    const int t   = threadIdx.x;
    const int b   = blockIdx.z;
    const int m0  = blockIdx.x * 128;
    const int fn0 = blockIdx.y * 128;

    __shared__ __align__(16) float As[2][8][136];   // transposed A tile [k][m], padded rows
    __shared__ __align__(16) float Bs[2][8][128];   // B tile [k][f]
    __shared__ unsigned smax[128];

    // A-load mapping: 2 threads per row, float4 each
    const int arow = t >> 1, ak4 = (t & 1) * 4;
    int p = m0 + arow; if (p > M_ - 1) p = M_ - 1;
    const int yc = p / 126, xc = p - yc * 126;
    const float* aBase = g_arc + (size_t)b * (L_ * L_ * IN_) + ((size_t)yc * L_ + xc) * IN_ + ak4;
    // B-load mapping
    const int brow = t >> 5, bc4 = (t & 31) * 4;
    const float* bBase = g_filtT + (size_t)b * (KC_ * FPAD_) + (size_t)brow * FPAD_ + fn0 + bc4;
    // compute mapping
    const int tidx = t & 15, tidy = t >> 4;

    unsigned long long acc[8][4];
#pragma unroll
    for (int m = 0; m < 8; m++)
#pragma unroll
        for (int n = 0; n < 4; n++) acc[m][n] = 0ull;

    // prologue: chunk 0 (tap=0 -> dy=dx=0, cb=0) into buffer 0
    {
        float4 av = *(const float4*)(aBase);
        float4 bv = *(const float4*)(bBase);
        float* asp = &As[0][0][0];
        asp[(ak4 + 0) * 136 + arow] = av.x;
        asp[(ak4 + 1) * 136 + arow] = av.y;
        asp[(ak4 + 2) * 136 + arow] = av.z;
        asp[(ak4 + 3) * 136 + arow] = av.w;
        *(float4*)&Bs[0][brow][bc4] = bv;
    }
    if (t < 128) smax[t] = 0u;
    __syncthreads();

    int buf = 0;
    for (int kc = 0; kc < 288; kc++) {
        float4 an, bn;
        const bool has = (kc + 1) < 288;
        if (has) {
            int kn = kc + 1;
            int tapn = kn >> 5;
            int dyn_ = tapn / 3, dxn = tapn - dyn_ * 3;
            int cbn = (kn & 31) * 8;
            an = *(const float4*)(aBase + ((size_t)dyn_ * L_ + dxn) * IN_ + cbn);
            bn = *(const float4*)(bBase + (size_t)kn * (8 * FPAD_));
        }
#pragma unroll
        for (int kk = 0; kk < 8; kk++) {
            float4 a0 = *(const float4*)&As[buf][kk][tidy * 8];
            float4 a1 = *(const float4*)&As[buf][kk][tidy * 8 + 4];
            ulonglong2 bq0 = *(const ulonglong2*)&Bs[buf][kk][tidx * 8];
            ulonglong2 bq1 = *(const ulonglong2*)&Bs[buf][kk][tidx * 8 + 4];
            float am[8] = {a0.x, a0.y, a0.z, a0.w, a1.x, a1.y, a1.z, a1.w};
#pragma unroll
            for (int m = 0; m < 8; m++) {
                unsigned long long ad = pk2(am[m], am[m]);
                acc[m][0] = fma2(ad, bq0.x, acc[m][0]);
                acc[m][1] = fma2(ad, bq0.y, acc[m][1]);
                acc[m][2] = fma2(ad, bq1.x, acc[m][2]);
                acc[m][3] = fma2(ad, bq1.y, acc[m][3]);
            }
        }
        if (has) {
            // store into the other buffer: its last readers finished before the
            // barrier at the end of the previous iteration — no WAR hazard.
            float* asp = &As[buf ^ 1][0][0];
            asp[(ak4 + 0) * 136 + arow] = an.x;
            asp[(ak4 + 1) * 136 + arow] = an.y;
            asp[(ak4 + 2) * 136 + arow] = an.z;
            asp[(ak4 + 3) * 136 + arow] = an.w;
            *(float4*)&Bs[buf ^ 1][brow][bc4] = bn;
            __syncthreads();
            buf ^= 1;
        }
    }

    // epilogue: max over this thread's valid pixels, reduce in smem, then global
    const int gmb = m0 + tidy * 8;
    const float NEG = __int_as_float(0xff800000);  // -inf
#pragma unroll
    for (int n2 = 0; n2 < 4; n2++) {
        float mlo = NEG, mhi = NEG;
#pragma unroll
        for (int m = 0; m < 8; m++) {
            if (gmb + m < M_) {
                unsigned long long v = acc[m][n2];
                float lo, hi;
                upk2(v, lo, hi);
                mlo = fmaxf(mlo, lo);
                mhi = fmaxf(mhi, hi);
            }
        }
        atomicMax(&smax[tidx * 8 + 2 * n2], fenc(mlo));
        atomicMax(&smax[tidx * 8 + 2 * n2 + 1], fenc(mhi));
    }
    __syncthreads();
    if (t < 128) atomicMax(&g_max[b * FPAD_ + fn0 + t], smax[t]);
}

// ---------------- final: transformed + leaky(max) ----------------
__global__ void k_final(const float* __restrict__ e1, const float* __restrict__ e2,
                        const float* __restrict__ it_W, const float* __restrict__ it_b,
                        float* __restrict__ out) {
    int b = blockIdx.y;
    __shared__ float in_sm[1024];
    int t = threadIdx.x;
    for (int idx = t; idx < 1024; idx += 256)
        in_sm[idx] = idx < 512 ? e1[b * 512 + idx] : e2[b * 512 + idx - 512];
    __syncthreads();
    int w = t >> 5, lane = t & 31;
    int f = blockIdx.x * 8 + w;
    if (f < F_) {
        float acc = 0.f;
        for (int it = 0; it < 32; it++) {
            int j = it * 32 + lane;
            acc += in_sm[j] * it_W[(size_t)f * 1024 + j];
        }
#pragma unroll
        for (int off = 16; off; off >>= 1) acc += __shfl_xor_sync(0xffffffffu, acc, off);
        if (!lane) {
            float tr = leaky(acc + it_b[f]);
            float mx = leaky(fdec(g_max[b * FPAD_ + f]));  // leaky after max (monotone)
            out[b * F_ + f] = tr + mx;
        }
    }
}

// ---------------- launch ----------------
extern "C" void kernel_launch(void* const* d_in, const int* in_sizes, int n_in,
                              void* d_out, int out_size) {
    const float* energy   = (const float*)d_in[0];
    const float* word_h   = (const float*)d_in[1];
    const float* e1       = (const float*)d_in[2];
    const float* e2       = (const float*)d_in[3];
    // d_in[4] = sent_len (unused)
    const float* rel_embs = (const float*)d_in[5];
    const float* arc_W    = (const float*)d_in[6];
    const float* arc_b    = (const float*)d_in[7];
    const float* ff_W     = (const float*)d_in[8];
    const float* ff_b     = (const float*)d_in[9];
    const float* fw1      = (const float*)d_in[10];
    const float* fb1      = (const float*)d_in[11];
    const float* it_W     = (const float*)d_in[12];
    const float* it_b     = (const float*)d_in[13];
    float* out = (float*)d_out;

    k_maxinit<<<2, 1024>>>();
    k_transpose<<<KW_, 256>>>(arc_W);
    k_relC<<<1, 256>>>(rel_embs);
    k_P<<<dim3(8, 2, B_), 256>>>(word_h);
    k_hidden<<<dim3(38, B_), 256>>>(e1, e2, ff_W, ff_b);
    k_arc<<<dim3(2, L_, B_), 256>>>(energy, arc_b);
    k_filt<<<57600, 256>>>(fw1, fb1);
    k_conv<<<dim3(125, 2, B_), 256>>>();
    k_final<<<dim3(25, B_), 256>>>(e1, e2, it_W, it_b, out);
}

// round 14
// speedup vs baseline: 1.9927x; 1.9927x over previous
#include <cuda_runtime.h>
#include <cuda_bf16.h>
#include <cstdint>
#include <cstddef>

// ---------------- problem constants ----------------
#define B_    8
#define R_    40
#define L_    128
#define IN_   256
#define WDIM_ 512
#define DREL_ 15
#define F_    200
#define HID_  300
#define KW_   1039      // 4*IN + DREL
#define FPAD_ 256       // filters padded to 256
#define KC_   2304      // 9 * 256 (taps x channels)
#define M_    15876     // 126*126 output pixels

// ---------------- device scratch (static: no allocation) ----------------
__device__ float          g_wt[KW_ * IN_];                     // arc_W transposed [1039][256]
__device__ float          g_C[R_ * IN_];
__device__ float          g_px[B_ * L_ * IN_];
__device__ float          g_py[B_ * L_ * IN_];
__device__ float          g_h[B_ * HID_];
__device__ __align__(16) __nv_bfloat16 g_arcH[(size_t)B_ * L_ * L_ * IN_];  // mem_bank hi, [b][y][x][c]
__device__ __align__(16) __nv_bfloat16 g_arcL[(size_t)B_ * L_ * L_ * IN_];  // mem_bank lo
__device__ __align__(16) __nv_bfloat16 g_fH[(size_t)B_ * FPAD_ * KC_];      // filters hi, [b][f][k], k=tap*256+c
__device__ __align__(16) __nv_bfloat16 g_fL[(size_t)B_ * FPAD_ * KC_];      // filters lo
__device__ unsigned       g_max[B_ * FPAD_];                   // ordered-encoded per-(b,f) max

// ---------------- helpers ----------------
__device__ __forceinline__ float leaky(float v) { return v >= 0.f ? v : 0.01f * v; }

__device__ __forceinline__ unsigned fenc(float x) {
    unsigned b = __float_as_uint(x);
    return (b & 0x80000000u) ? ~b : (b | 0x80000000u);
}
__device__ __forceinline__ float fdec(unsigned u) {
    return __uint_as_float((u & 0x80000000u) ? (u & 0x7fffffffu) : ~u);
}

// packed fp32x2 (FFMA2)
__device__ __forceinline__ unsigned long long pk2(float lo, float hi) {
    unsigned long long r;
    asm("mov.b64 %0, {%1, %2};" : "=l"(r) : "f"(lo), "f"(hi));
    return r;
}
__device__ __forceinline__ void upk2(unsigned long long v, float& lo, float& hi) {
    asm("mov.b64 {%0, %1}, %2;" : "=f"(lo), "=f"(hi) : "l"(v));
}
__device__ __forceinline__ unsigned long long fma2(unsigned long long a,
                                                   unsigned long long b,
                                                   unsigned long long c) {
    unsigned long long d;
    asm("fma.rn.f32x2 %0, %1, %2, %3;" : "=l"(d) : "l"(a), "l"(b), "l"(c));
    return d;
}

__device__ __forceinline__ uint32_t smem_u32(const void* p) {
    uint32_t a;
    asm("{ .reg .u64 tmp; cvta.to.shared.u64 tmp, %1; cvt.u32.u64 %0, tmp; }" : "=r"(a) : "l"(p));
    return a;
}

// ---------------- sm_80-era tensor-core primitives (legal on .target sm_103) ----------------
__device__ __forceinline__ void ldsm4(uint32_t* r, uint32_t addr) {
    asm volatile("ldmatrix.sync.aligned.m8n8.x4.shared.b16 {%0,%1,%2,%3}, [%4];"
        : "=r"(r[0]), "=r"(r[1]), "=r"(r[2]), "=r"(r[3]) : "r"(addr));
}
__device__ __forceinline__ void mma16816(float* d, const uint32_t* a, const uint32_t* b) {
    asm volatile("mma.sync.aligned.m16n8k16.row.col.f32.bf16.bf16.f32 "
        "{%0,%1,%2,%3}, {%4,%5,%6,%7}, {%8,%9}, {%0,%1,%2,%3};"
        : "+f"(d[0]), "+f"(d[1]), "+f"(d[2]), "+f"(d[3])
        : "r"(a[0]), "r"(a[1]), "r"(a[2]), "r"(a[3]), "r"(b[0]), "r"(b[1]));
}
#define CPA16(dst, src) \
    asm volatile("cp.async.cg.shared.global [%0], [%1], 16;" :: "r"(dst), "l"(src))
#define CPA_COMMIT() asm volatile("cp.async.commit_group;" ::: "memory")
#define CPA_WAIT1()  asm volatile("cp.async.wait_group 1;" ::: "memory")
#define CPA_WAIT0()  asm volatile("cp.async.wait_group 0;" ::: "memory")

// ---------------- tiny precompute kernels ----------------
__global__ void k_transpose(const float* __restrict__ arc_W) {
    int k = blockIdx.x, o = threadIdx.x;
    g_wt[k * IN_ + o] = arc_W[o * KW_ + k];
}

__global__ void k_relC(const float* __restrict__ rel_embs) {
    int o = threadIdx.x;
    for (int r = 0; r < R_; r++) {
        float s = 0.f;
#pragma unroll
        for (int d = 0; d < DREL_; d++)
            s += rel_embs[r * DREL_ + d] * g_wt[(4 * IN_ + d) * IN_ + o];
        g_C[r * IN_ + o] = s;
    }
}

// Px/Py: 16 groups of 8 tokens -> 256 CTAs
__global__ void k_P(const float* __restrict__ word_h) {
    int tg = blockIdx.x;
    int which = blockIdx.y;   // 0:Px 1:Py
    int b = blockIdx.z;
    __shared__ float wh[8][WDIM_];
    int t = threadIdx.x;
    int t0 = tg * 8;
    for (int idx = t; idx < 8 * WDIM_; idx += 256) {
        int tt = idx >> 9, k = idx & 511;
        wh[tt][k] = word_h[((size_t)(b * L_ + t0 + tt)) * WDIM_ + k];
    }
    __syncthreads();
    float acc[8];
#pragma unroll
    for (int i = 0; i < 8; i++) acc[i] = 0.f;
    const float* wtp = g_wt + (size_t)which * WDIM_ * IN_ + t;
#pragma unroll 8
    for (int k = 0; k < WDIM_; k++) {
        float w = wtp[(size_t)k * IN_];
#pragma unroll
        for (int tt = 0; tt < 8; tt++) acc[tt] += w * wh[tt][k];
    }
    float* dst = (which ? g_py : g_px) + ((size_t)(b * L_ + t0)) * IN_ + t;
#pragma unroll
    for (int tt = 0; tt < 8; tt++) dst[(size_t)tt * IN_] = acc[tt];
}

__global__ void k_hidden(const float* __restrict__ e1, const float* __restrict__ e2,
                         const float* __restrict__ ff_W, const float* __restrict__ ff_b) {
    int b = blockIdx.y;
    __shared__ float in_sm[1024];
    int t = threadIdx.x;
    for (int idx = t; idx < 1024; idx += 256)
        in_sm[idx] = idx < 512 ? e1[b * 512 + idx] : e2[b * 512 + idx - 512];
    __syncthreads();
    int w = t >> 5, lane = t & 31;
    int k = blockIdx.x * 8 + w;
    if (k < HID_) {
        float acc = 0.f;
        for (int it = 0; it < 32; it++) {
            int j = it * 32 + lane;
            acc += in_sm[j] * ff_W[(size_t)k * 1024 + j];
        }
#pragma unroll
        for (int off = 16; off; off >>= 1) acc += __shfl_xor_sync(0xffffffffu, acc, off);
        if (!lane) g_h[b * HID_ + k] = leaky(acc + ff_b[k]);
    }
}

// ---------------- arc / mem_bank: emit bf16 hi/lo split ----------------
__global__ void k_arc(const float* __restrict__ energy, const float* __restrict__ arc_b) {
    int b = blockIdx.z, i = blockIdx.y, j0 = blockIdx.x * 64;
    __shared__ __align__(16) float e_sm[R_][64];
    __shared__ float m_sm[64];
    int t = threadIdx.x;
    const float* ep = energy + (((size_t)b * R_) * L_ + i) * L_ + j0;
    for (int idx = t; idx < R_ * 64; idx += 256) {
        int r = idx >> 6, j = idx & 63;
        float v = ep[(size_t)r * L_ * L_ + j];
        e_sm[r][j] = v < 0.f ? 0.f : v;
    }
    __syncthreads();
    if (t < 64) {
        float s = 0.f;
#pragma unroll
        for (int r = 0; r < R_; r++) s += e_sm[r][t];
        m_sm[t] = s;
    }
    unsigned long long Creg2[R_];
#pragma unroll
    for (int r = 0; r < R_; r++) {
        float c = g_C[r * IN_ + t];
        Creg2[r] = pk2(c, c);
    }
    float py = g_py[((size_t)(b * L_ + i)) * IN_ + t];
    float bias = arc_b[t];
    __syncthreads();

    size_t base = (((size_t)(b * L_ + i)) * L_ + j0) * IN_ + t;
    const float* pxp = g_px + ((size_t)(b * L_) + j0) * IN_ + t;
#pragma unroll 4
    for (int q = 0; q < 16; q++) {
        unsigned long long acc01 = 0ull, acc23 = 0ull;
#pragma unroll
        for (int r = 0; r < R_; r++) {
            ulonglong2 ev = *(const ulonglong2*)&e_sm[r][q * 4];
            acc01 = fma2(ev.x, Creg2[r], acc01);
            acc23 = fma2(ev.y, Creg2[r], acc23);
        }
        float av[4];
        upk2(acc01, av[0], av[1]);
        upk2(acc23, av[2], av[3]);
#pragma unroll
        for (int u = 0; u < 4; u++) {
            int j = q * 4 + u;
            float v = leaky(m_sm[j] * (pxp[(size_t)j * IN_] + py) + av[u] + bias);
            __nv_bfloat16 hi = __float2bfloat16(v);
            float lo = v - __bfloat162float(hi);
            g_arcH[base + (size_t)j * IN_] = hi;
            g_arcL[base + (size_t)j * IN_] = __float2bfloat16(lo);
        }
    }
}

// zero filter arrays (pad rows f >= 200 must be 0)
__global__ void k_zero() {
    size_t idx = (size_t)blockIdx.x * 256 + threadIdx.x;   // uint4 index
    const size_t n = ((size_t)B_ * FPAD_ * KC_ * 2) / 16;  // per array
    if (idx < n) ((uint4*)g_fH)[idx] = make_uint4(0, 0, 0, 0);
    else         ((uint4*)g_fL)[idx - n] = make_uint4(0, 0, 0, 0);
}

// filters: hi/lo bf16 at [b][f][tap*256+c]
__global__ void k_filt(const float* __restrict__ fw1, const float* __restrict__ fb1) {
    __shared__ float h_sm[B_][HID_];
    int t = threadIdx.x;
    for (int idx = t; idx < B_ * HID_; idx += 256)
        h_sm[idx / HID_][idx % HID_] = g_h[idx];
    __syncthreads();
    int w = t >> 5, lane = t & 31;
    int row = blockIdx.x * 8 + w;          // (f*256+c)*9+tap
    float acc[8];
#pragma unroll
    for (int b = 0; b < 8; b++) acc[b] = 0.f;
    const float* wp = fw1 + (size_t)row * HID_;
#pragma unroll
    for (int it = 0; it < 10; it++) {
        int hh = it * 32 + lane;
        float wv = (hh < HID_) ? wp[hh] : 0.f;
        int hc = (hh < HID_) ? hh : 0;
#pragma unroll
        for (int b = 0; b < 8; b++) acc[b] += wv * h_sm[b][hc];
    }
#pragma unroll
    for (int off = 16; off; off >>= 1)
#pragma unroll
        for (int b = 0; b < 8; b++) acc[b] += __shfl_xor_sync(0xffffffffu, acc[b], off);
    if (!lane) {
        int f = row / 2304, rem = row - f * 2304;
        int c = rem / 9, tap = rem - c * 9;
        float bias = fb1[row];
        size_t kk = (size_t)tap * 256 + c;
#pragma unroll
        for (int b = 0; b < 8; b++) {
            float v = leaky(acc[b] + bias);
            __nv_bfloat16 hi = __float2bfloat16(v);
            float lo = v - __bfloat162float(hi);
            size_t o = ((size_t)b * FPAD_ + f) * KC_ + kk;
            g_fH[o] = hi;
            g_fL[o] = __float2bfloat16(lo);
        }
    }
}

__global__ void k_maxinit() { g_max[blockIdx.x * 1024 + threadIdx.x] = 0u; }

// ---------------- conv: mma.sync HMMA implicit GEMM, bf16 split, fused leaky+max ----------
// CTA: M=128 pixels x N=256 filters, 512 threads (4x4 warps, warp tile 32x64).
// K = 2304 in 72 chunks of 32. smem rows padded to 80B (bank-conflict-free ldmatrix).
// Products per chunk: AH*BH + AH*BL + AL*BH. cp.async double-buffered.
#define CHUNKS_  72
#define ROWB_    80                       // padded row stride (bytes) = 40 bf16
#define OFF_AH_  0
#define OFF_AL_  10240
#define OFF_BH_  20480
#define OFF_BL_  40960
#define BUFSZ_   61440
#define SMEM_DYN_ 122880

__global__ __launch_bounds__(512, 1) void k_conv() {
    extern __shared__ __align__(128) unsigned char dyn[];
    __shared__ unsigned smax[256];

    const int t = threadIdx.x;
    const int wid = t >> 5, lane = t & 31;
    const int wm = wid >> 2, wn = wid & 3;      // warp grid 4(M) x 4(N)
    const int b = blockIdx.z;
    const int m0 = blockIdx.x * 128;
    const uint32_t smb = smem_u32(dyn);

    if (t < 256) smax[t] = 0u;

    // ---- per-thread gmem/smem load geometry (row = t>>2, 16B seg = t&3) ----
    const int lrow = t >> 2;                    // 0..127
    const int lseg = t & 3;
    int p = m0 + lrow; if (p > M_ - 1) p = M_ - 1;
    const int py_ = p / 126, px_ = p - py_ * 126;
    const size_t aGm = ((size_t)b * (L_ * L_) + (size_t)py_ * L_ + px_) * IN_ + lseg * 8;
    const uint32_t aSm = (uint32_t)(lrow * ROWB_ + lseg * 16);
    const size_t bGm0 = ((size_t)b * FPAD_ + lrow) * KC_ + (size_t)lseg * 8;
    const size_t bGm1 = ((size_t)b * FPAD_ + lrow + 128) * KC_ + (size_t)lseg * 8;
    const uint32_t bSm0 = aSm;
    const uint32_t bSm1 = aSm + 128 * ROWB_;

    // ---- ldmatrix lane addressing ----
    const int arow16 = (lane & 7) | (lane & 8);            // row within 16-tile
    const uint32_t aLd = (uint32_t)((wm * 32 + arow16) * ROWB_ + (lane >> 4) * 16);
    const uint32_t bLd = (uint32_t)((wn * 64 + (lane >> 4) * 8 + (lane & 7)) * ROWB_
                                    + ((lane >> 3) & 1) * 16);

    float acc[2][8][4];
#pragma unroll
    for (int i = 0; i < 2; i++)
#pragma unroll
        for (int j = 0; j < 8; j++)
#pragma unroll
            for (int v = 0; v < 4; v++) acc[i][j][v] = 0.f;

    // ---- async tile loader ----
    auto issue = [&](int c, int buf) {
        const int tap = c >> 3, cb = c & 7;
        const int dy = tap / 3, dx = tap - dy * 3;
        const size_t kA = ((size_t)dy * L_ + dx) * IN_ + cb * 32;
        const size_t kB = (size_t)tap * 256 + cb * 32;
        const uint32_t so = smb + (uint32_t)buf * BUFSZ_;
        CPA16(so + OFF_AH_ + aSm, g_arcH + aGm + kA);
        CPA16(so + OFF_AL_ + aSm, g_arcL + aGm + kA);
        CPA16(so + OFF_BH_ + bSm0, g_fH + bGm0 + kB);
        CPA16(so + OFF_BH_ + bSm1, g_fH + bGm1 + kB);
        CPA16(so + OFF_BL_ + bSm0, g_fL + bGm0 + kB);
        CPA16(so + OFF_BL_ + bSm1, g_fL + bGm1 + kB);
    };

    issue(0, 0);
    CPA_COMMIT();

    for (int cc = 0; cc < CHUNKS_; cc++) {
        const int buf = cc & 1;
        if (cc + 1 < CHUNKS_) {
            issue(cc + 1, buf ^ 1);
            CPA_COMMIT();
            CPA_WAIT1();
        } else {
            CPA_WAIT0();
        }
        __syncthreads();

        const uint32_t base = smb + (uint32_t)buf * BUFSZ_;
#pragma unroll
        for (int pr = 0; pr < 3; pr++) {
            const uint32_t aB = base + (pr < 2 ? OFF_AH_ : OFF_AL_);
            const uint32_t bB = base + (pr == 1 ? OFF_BL_ : OFF_BH_);
#pragma unroll
            for (int ks = 0; ks < 2; ks++) {
                uint32_t a0[4], a1[4];
                ldsm4(a0, aB + aLd + ks * 32);
                ldsm4(a1, aB + aLd + 16 * ROWB_ + ks * 32);
#pragma unroll
                for (int bt = 0; bt < 4; bt++) {
                    uint32_t bb[4];
                    ldsm4(bb, bB + bLd + bt * 16 * ROWB_ + ks * 32);
                    mma16816(acc[0][2 * bt],     a0, bb);
                    mma16816(acc[0][2 * bt + 1], a0, bb + 2);
                    mma16816(acc[1][2 * bt],     a1, bb);
                    mma16816(acc[1][2 * bt + 1], a1, bb + 2);
                }
            }
        }
        __syncthreads();
    }

    // ---- epilogue: leaky+max over valid pixels, shfl-reduce, atomics ----
    const float NEG = __int_as_float(0xff800000);
    const int r0 = m0 + wm * 32 + (lane >> 2);
    const bool v00 = (r0 < M_), v01 = (r0 + 8 < M_);
    const bool v10 = (r0 + 16 < M_), v11 = (r0 + 24 < M_);
#pragma unroll
    for (int nt = 0; nt < 8; nt++) {
        float x0 = NEG, x1 = NEG;
        if (v00) { x0 = fmaxf(x0, acc[0][nt][0]); x1 = fmaxf(x1, acc[0][nt][1]); }
        if (v01) { x0 = fmaxf(x0, acc[0][nt][2]); x1 = fmaxf(x1, acc[0][nt][3]); }
        if (v10) { x0 = fmaxf(x0, acc[1][nt][0]); x1 = fmaxf(x1, acc[1][nt][1]); }
        if (v11) { x0 = fmaxf(x0, acc[1][nt][2]); x1 = fmaxf(x1, acc[1][nt][3]); }
        x0 = leaky(x0); x1 = leaky(x1);
#pragma unroll
        for (int off = 16; off >= 4; off >>= 1) {
            x0 = fmaxf(x0, __shfl_xor_sync(0xffffffffu, x0, off));
            x1 = fmaxf(x1, __shfl_xor_sync(0xffffffffu, x1, off));
        }
        if (lane < 4) {
            int f = wn * 64 + nt * 8 + 2 * lane;
            atomicMax(&smax[f], fenc(x0));
            atomicMax(&smax[f + 1], fenc(x1));
        }
    }
    __syncthreads();
    if (t < 256) atomicMax(&g_max[b * FPAD_ + t], smax[t]);
}

// ---------------- final: transformed + leaky(max) ----------------
__global__ void k_final(const float* __restrict__ e1, const float* __restrict__ e2,
                        const float* __restrict__ it_W, const float* __restrict__ it_b,
                        float* __restrict__ out) {
    int b = blockIdx.y;
    __shared__ float in_sm[1024];
    int t = threadIdx.x;
    for (int idx = t; idx < 1024; idx += 256)
        in_sm[idx] = idx < 512 ? e1[b * 512 + idx] : e2[b * 512 + idx - 512];
    __syncthreads();
    int w = t >> 5, lane = t & 31;
    int f = blockIdx.x * 8 + w;
    if (f < F_) {
        float acc = 0.f;
        for (int it = 0; it < 32; it++) {
            int j = it * 32 + lane;
            acc += in_sm[j] * it_W[(size_t)f * 1024 + j];
        }
#pragma unroll
        for (int off = 16; off; off >>= 1) acc += __shfl_xor_sync(0xffffffffu, acc, off);
        if (!lane) {
            float tr = leaky(acc + it_b[f]);
            float mx = leaky(fdec(g_max[b * FPAD_ + f]));  // leaky after max (monotone)
            out[b * F_ + f] = tr + mx;
        }
    }
}

// ---------------- launch ----------------
extern "C" void kernel_launch(void* const* d_in, const int* in_sizes, int n_in,
                              void* d_out, int out_size) {
    const float* energy   = (const float*)d_in[0];
    const float* word_h   = (const float*)d_in[1];
    const float* e1       = (const float*)d_in[2];
    const float* e2       = (const float*)d_in[3];
    // d_in[4] = sent_len (unused)
    const float* rel_embs = (const float*)d_in[5];
    const float* arc_W    = (const float*)d_in[6];
    const float* arc_b    = (const float*)d_in[7];
    const float* ff_W     = (const float*)d_in[8];
    const float* ff_b     = (const float*)d_in[9];
    const float* fw1      = (const float*)d_in[10];
    const float* fb1      = (const float*)d_in[11];
    const float* it_W     = (const float*)d_in[12];
    const float* it_b     = (const float*)d_in[13];
    float* out = (float*)d_out;

    // idempotent, host-side, capture-safe
    cudaFuncSetAttribute(k_conv, cudaFuncAttributeMaxDynamicSharedMemorySize, SMEM_DYN_);

    k_maxinit<<<2, 1024>>>();
    k_zero<<<(int)(((size_t)B_ * FPAD_ * KC_ * 2 * 2 / 16 + 255) / 256), 256>>>();
    k_transpose<<<KW_, 256>>>(arc_W);
    k_relC<<<1, 256>>>(rel_embs);
    k_P<<<dim3(16, 2, B_), 256>>>(word_h);
    k_hidden<<<dim3(38, B_), 256>>>(e1, e2, ff_W, ff_b);
    k_arc<<<dim3(2, L_, B_), 256>>>(energy, arc_b);
    k_filt<<<57600, 256>>>(fw1, fb1);
    k_conv<<<dim3(125, 1, B_), 512, SMEM_DYN_>>>();
    k_final<<<dim3(25, B_), 256>>>(e1, e2, it_W, it_b, out);
}